// round 2
// baseline (speedup 1.0000x reference)
#include <cuda_runtime.h>
#include <cstdint>

#define NN   8192
#define IND  128
#define OUTD 64
#define NSPLIT 8
#define JCHUNK (NN / NSPLIT)   // 1024 j-columns per split

// static device scratch (no allocations allowed)
__device__ float g_Wh[(size_t)NN * OUTD];
__device__ float g_s1[NN];
__device__ float g_s2[NN];
__device__ float g_part[(size_t)NSPLIT * NN * OUTD];  // partial accumulators (16.8 MB)
__device__ float g_lp[(size_t)NSPLIT * NN];           // partial row sums

__device__ __forceinline__ unsigned long long pk2(float lo, float hi) {
    unsigned long long r;
    asm("mov.b64 %0, {%1, %2};" : "=l"(r) : "f"(lo), "f"(hi));
    return r;
}
__device__ __forceinline__ void ffma2(unsigned long long& d, unsigned long long a, unsigned long long b) {
    asm("fma.rn.f32x2 %0, %1, %2, %0;" : "+l"(d) : "l"(a), "l"(b));
}
__device__ __forceinline__ float2 upk2(unsigned long long v) {
    float2 r;
    asm("mov.b64 {%0, %1}, %2;" : "=f"(r.x), "=f"(r.y) : "l"(v));
    return r;
}

// ---------------------------------------------------------------------------
// K1: Wh = x @ W;  s1 = Wh @ a[:64];  s2 = Wh @ a[64:]
// 256 blocks x 128 threads, 32 rows/block, thread tile 4 rows x 4 dims.
// ---------------------------------------------------------------------------
__global__ __launch_bounds__(128) void k1_proj(const float* __restrict__ x,
                                               const float* __restrict__ W,
                                               const float* __restrict__ a) {
    __shared__ float W_sm[IND][OUTD];
    __shared__ float x_sm[32][33];

    const int t  = threadIdx.x;
    const int i0 = blockIdx.x * 32;
    const int dl = t & 15;
    const int rl = t >> 4;

    {
        const float4* src = (const float4*)W;
        float4* dst = (float4*)&W_sm[0][0];
#pragma unroll
        for (int q = 0; q < 16; ++q) dst[t + 128 * q] = src[t + 128 * q];
    }

    float acc[4][4];
#pragma unroll
    for (int rr = 0; rr < 4; ++rr)
#pragma unroll
        for (int dd = 0; dd < 4; ++dd) acc[rr][dd] = 0.f;

    for (int k0 = 0; k0 < IND; k0 += 32) {
        __syncthreads();
#pragma unroll
        for (int q = 0; q < 8; ++q) {
            int idx = t + 128 * q;
            int r = idx >> 5, kk = idx & 31;
            x_sm[r][kk] = x[(size_t)(i0 + r) * IND + k0 + kk];
        }
        __syncthreads();
#pragma unroll
        for (int kk = 0; kk < 32; ++kk) {
            float4 w = *(const float4*)&W_sm[k0 + kk][dl * 4];
#pragma unroll
            for (int rr = 0; rr < 4; ++rr) {
                float xv = x_sm[rl * 4 + rr][kk];
                acc[rr][0] += xv * w.x;
                acc[rr][1] += xv * w.y;
                acc[rr][2] += xv * w.z;
                acc[rr][3] += xv * w.w;
            }
        }
    }

    const float* a1 = a;
    const float* a2 = a + OUTD;
#pragma unroll
    for (int rr = 0; rr < 4; ++rr) {
        int row = i0 + rl * 4 + rr;
        *(float4*)&g_Wh[(size_t)row * OUTD + dl * 4] =
            make_float4(acc[rr][0], acc[rr][1], acc[rr][2], acc[rr][3]);
        float4 av1 = *(const float4*)&a1[dl * 4];
        float4 av2 = *(const float4*)&a2[dl * 4];
        float v1 = acc[rr][0] * av1.x + acc[rr][1] * av1.y + acc[rr][2] * av1.z + acc[rr][3] * av1.w;
        float v2 = acc[rr][0] * av2.x + acc[rr][1] * av2.y + acc[rr][2] * av2.z + acc[rr][3] * av2.w;
#pragma unroll
        for (int o = 8; o >= 1; o >>= 1) {
            v1 += __shfl_xor_sync(0xffffffffu, v1, o, 16);
            v2 += __shfl_xor_sync(0xffffffffu, v2, o, 16);
        }
        if (dl == 0) { g_s1[row] = v1; g_s2[row] = v2; }
    }
}

// ---------------------------------------------------------------------------
// K2: fused attention, j-split across blockIdx.y (8 splits of 1024 columns).
// Partial sums (no normalization) written to g_part / g_lp.
// 128 threads: FMA thread tile = 2 rows x 8 dims (f32x2 packed FMA).
//   dl = t&7 (dims dl*8..dl*8+7), rl = t>>3 (rows rl*2, rl*2+1)
// p-compute: pr = t>>2 (row), quarter pc = (t&3)*16.
// ---------------------------------------------------------------------------
__global__ __launch_bounds__(128) void k2_attn(const int* __restrict__ adj) {
    __shared__ float Wh_sm[64][68];
    __shared__ float p_sm[32][68];
    __shared__ float lpart[128];

    const int t     = threadIdx.x;
    const int i0    = blockIdx.x * 32;
    const int split = blockIdx.y;
    const int js    = split * JCHUNK;
    const int dl = t & 7;
    const int rl = t >> 3;    // 0..15
    const int pr = t >> 2;    // 0..31
    const int pc = (t & 3) * 16;

    const float s1v = g_s1[i0 + pr];
    const int* adjrow = adj + (size_t)(i0 + pr) * NN;

    float lacc = 0.f;
    unsigned long long acc[2][4];
#pragma unroll
    for (int rr = 0; rr < 2; ++rr)
#pragma unroll
        for (int q = 0; q < 4; ++q) acc[rr][q] = 0ull;

    for (int tile = 0; tile < JCHUNK / 64; ++tile) {
        const int j0 = js + tile * 64;
        __syncthreads();   // protect previous tile's smem reads

        // load Wh tile: thread pair (t>>1) owns row j0+(t>>1), half (t&1)
        {
            const int jr = t >> 1;
            const int ch = (t & 1) * 32;
            const float4* src = (const float4*)(g_Wh + (size_t)(j0 + jr) * OUTD + ch);
#pragma unroll
            for (int q = 0; q < 8; ++q) *(float4*)&Wh_sm[jr][ch + 4 * q] = src[q];
        }
        // compute p tile: 16 columns per thread
        {
            const int base = j0 + pc;
            const int4*   a4p = (const int4*)(adjrow + base);
            const float4* s4p = (const float4*)(g_s2 + base);
#pragma unroll
            for (int k = 0; k < 4; ++k) {
                int4   a4 = a4p[k];
                float4 s4 = s4p[k];
                float4 pv;
                float e;
                e = s1v + s4.x; e = e > 0.f ? e : 0.2f * e; pv.x = a4.x ? __expf(e) : 0.f;
                e = s1v + s4.y; e = e > 0.f ? e : 0.2f * e; pv.y = a4.y ? __expf(e) : 0.f;
                e = s1v + s4.z; e = e > 0.f ? e : 0.2f * e; pv.z = a4.z ? __expf(e) : 0.f;
                e = s1v + s4.w; e = e > 0.f ? e : 0.2f * e; pv.w = a4.w ? __expf(e) : 0.f;
                lacc += (pv.x + pv.y) + (pv.z + pv.w);
                *(float4*)&p_sm[pr][pc + 4 * k] = pv;
            }
        }
        __syncthreads();

        // acc[r][d] += p[r][j] * Wh[j][d]
        for (int jb = 0; jb < 64; jb += 4) {
            float4 pq0 = *(const float4*)&p_sm[rl * 2 + 0][jb];
            float4 pq1 = *(const float4*)&p_sm[rl * 2 + 1][jb];
#pragma unroll
            for (int m = 0; m < 4; ++m) {
                const int j = jb + m;
                float4 w0 = *(const float4*)&Wh_sm[j][dl * 8];
                float4 w1 = *(const float4*)&Wh_sm[j][dl * 8 + 4];
                unsigned long long wl0 = pk2(w0.x, w0.y);
                unsigned long long wl1 = pk2(w0.z, w0.w);
                unsigned long long wl2 = pk2(w1.x, w1.y);
                unsigned long long wl3 = pk2(w1.z, w1.w);
                float pv0 = (m == 0) ? pq0.x : (m == 1) ? pq0.y : (m == 2) ? pq0.z : pq0.w;
                float pv1 = (m == 0) ? pq1.x : (m == 1) ? pq1.y : (m == 2) ? pq1.z : pq1.w;
                unsigned long long pp0 = pk2(pv0, pv0);
                unsigned long long pp1 = pk2(pv1, pv1);
                ffma2(acc[0][0], wl0, pp0);
                ffma2(acc[0][1], wl1, pp0);
                ffma2(acc[0][2], wl2, pp0);
                ffma2(acc[0][3], wl3, pp0);
                ffma2(acc[1][0], wl0, pp1);
                ffma2(acc[1][1], wl1, pp1);
                ffma2(acc[1][2], wl2, pp1);
                ffma2(acc[1][3], wl3, pp1);
            }
        }
    }

    // partial l: 4 threads per row
    lpart[t] = lacc;
    __syncthreads();
    if (t < 32) {
        float l = lpart[4 * t] + lpart[4 * t + 1] + lpart[4 * t + 2] + lpart[4 * t + 3];
        g_lp[(size_t)split * NN + i0 + t] = l;
    }

    // write raw partial accumulators
#pragma unroll
    for (int rr = 0; rr < 2; ++rr) {
        const int row = i0 + rl * 2 + rr;
        float* dst = &g_part[((size_t)split * NN + row) * OUTD + dl * 8];
        float2 v0 = upk2(acc[rr][0]);
        float2 v1 = upk2(acc[rr][1]);
        float2 v2 = upk2(acc[rr][2]);
        float2 v3 = upk2(acc[rr][3]);
        *(float4*)&dst[0] = make_float4(v0.x, v0.y, v1.x, v1.y);
        *(float4*)&dst[4] = make_float4(v2.x, v2.y, v3.x, v3.y);
    }
}

// ---------------------------------------------------------------------------
// K3: reduce 8 partials, normalize, ELU. One float4 (4 dims) per thread.
// ---------------------------------------------------------------------------
__global__ __launch_bounds__(128) void k3_reduce(float* __restrict__ out) {
    const int q   = blockIdx.x * 128 + threadIdx.x;   // 0 .. N*OUTD/4-1
    const int row = q >> 4;           // OUTD/4 = 16 quads per row
    const int c4  = (q & 15) * 4;

    float l = 0.f;
#pragma unroll
    for (int s = 0; s < NSPLIT; ++s) l += g_lp[(size_t)s * NN + row];
    const float inv = 1.0f / l;

    float4 acc = make_float4(0.f, 0.f, 0.f, 0.f);
#pragma unroll
    for (int s = 0; s < NSPLIT; ++s) {
        float4 v = *(const float4*)&g_part[((size_t)s * NN + row) * OUTD + c4];
        acc.x += v.x; acc.y += v.y; acc.z += v.z; acc.w += v.w;
    }
    acc.x *= inv; acc.y *= inv; acc.z *= inv; acc.w *= inv;
    acc.x = acc.x > 0.f ? acc.x : expm1f(acc.x);
    acc.y = acc.y > 0.f ? acc.y : expm1f(acc.y);
    acc.z = acc.z > 0.f ? acc.z : expm1f(acc.z);
    acc.w = acc.w > 0.f ? acc.w : expm1f(acc.w);
    *(float4*)&out[(size_t)row * OUTD + c4] = acc;
}

extern "C" void kernel_launch(void* const* d_in, const int* in_sizes, int n_in,
                              void* d_out, int out_size) {
    const float* x   = (const float*)d_in[0];
    const int*   adj = (const int*)d_in[1];
    const float* W   = (const float*)d_in[2];
    const float* a   = (const float*)d_in[3];
    float* out = (float*)d_out;

    k1_proj<<<256, 128>>>(x, W, a);
    k2_attn<<<dim3(256, NSPLIT), 128>>>(adj);
    k3_reduce<<<(NN * OUTD / 4) / 128, 128>>>(out);
}

// round 3
// speedup vs baseline: 2.2304x; 2.2304x over previous
#include <cuda_runtime.h>
#include <cstdint>

#define NN   8192
#define IND  128
#define OUTD 64
#define NSPLIT 16
#define JCHUNK (NN / NSPLIT)   // 512 j-columns per split
#define JT 32                  // j tile

// static device scratch (no allocations allowed)
__device__ float g_Wh[(size_t)NN * OUTD];
__device__ float g_s1[NN];
__device__ float g_s2[NN];
__device__ float g_part[(size_t)NSPLIT * NN * OUTD];  // 33.5 MB partials
__device__ float g_lp[(size_t)NSPLIT * NN];

__device__ __forceinline__ void ffma2(unsigned long long& d, unsigned long long a, unsigned long long b) {
    asm("fma.rn.f32x2 %0, %1, %2, %0;" : "+l"(d) : "l"(a), "l"(b));
}
__device__ __forceinline__ float2 upk2(unsigned long long v) {
    float2 r;
    asm("mov.b64 {%0, %1}, %2;" : "=f"(r.x), "=f"(r.y) : "l"(v));
    return r;
}
// store {v,v} to shared with a single STS.64, no packing movs
__device__ __forceinline__ void sts_dup(void* p, float v) {
    unsigned a = (unsigned)__cvta_generic_to_shared(p);
    asm volatile("st.shared.v2.f32 [%0], {%1, %1};" :: "r"(a), "f"(v) : "memory");
}

// ---------------------------------------------------------------------------
// K1: Wh = x @ W;  s1 = Wh @ a[:64];  s2 = Wh @ a[64:]
// ---------------------------------------------------------------------------
__global__ __launch_bounds__(128) void k1_proj(const float* __restrict__ x,
                                               const float* __restrict__ W,
                                               const float* __restrict__ a) {
    __shared__ float W_sm[IND][OUTD];
    __shared__ float x_sm[32][33];

    const int t  = threadIdx.x;
    const int i0 = blockIdx.x * 32;
    const int dl = t & 15;
    const int rl = t >> 4;

    {
        const float4* src = (const float4*)W;
        float4* dst = (float4*)&W_sm[0][0];
#pragma unroll
        for (int q = 0; q < 16; ++q) dst[t + 128 * q] = src[t + 128 * q];
    }

    float acc[4][4];
#pragma unroll
    for (int rr = 0; rr < 4; ++rr)
#pragma unroll
        for (int dd = 0; dd < 4; ++dd) acc[rr][dd] = 0.f;

    for (int k0 = 0; k0 < IND; k0 += 32) {
        __syncthreads();
#pragma unroll
        for (int q = 0; q < 8; ++q) {
            int idx = t + 128 * q;
            int r = idx >> 5, kk = idx & 31;
            x_sm[r][kk] = x[(size_t)(i0 + r) * IND + k0 + kk];
        }
        __syncthreads();
#pragma unroll
        for (int kk = 0; kk < 32; ++kk) {
            float4 w = *(const float4*)&W_sm[k0 + kk][dl * 4];
#pragma unroll
            for (int rr = 0; rr < 4; ++rr) {
                float xv = x_sm[rl * 4 + rr][kk];
                acc[rr][0] += xv * w.x;
                acc[rr][1] += xv * w.y;
                acc[rr][2] += xv * w.z;
                acc[rr][3] += xv * w.w;
            }
        }
    }

    const float* a1 = a;
    const float* a2 = a + OUTD;
#pragma unroll
    for (int rr = 0; rr < 4; ++rr) {
        int row = i0 + rl * 4 + rr;
        *(float4*)&g_Wh[(size_t)row * OUTD + dl * 4] =
            make_float4(acc[rr][0], acc[rr][1], acc[rr][2], acc[rr][3]);
        float4 av1 = *(const float4*)&a1[dl * 4];
        float4 av2 = *(const float4*)&a2[dl * 4];
        float v1 = acc[rr][0] * av1.x + acc[rr][1] * av1.y + acc[rr][2] * av1.z + acc[rr][3] * av1.w;
        float v2 = acc[rr][0] * av2.x + acc[rr][1] * av2.y + acc[rr][2] * av2.z + acc[rr][3] * av2.w;
#pragma unroll
        for (int o = 8; o >= 1; o >>= 1) {
            v1 += __shfl_xor_sync(0xffffffffu, v1, o, 16);
            v2 += __shfl_xor_sync(0xffffffffu, v2, o, 16);
        }
        if (dl == 0) { g_s1[row] = v1; g_s2[row] = v2; }
    }
}

// ---------------------------------------------------------------------------
// K2: fused attention, j-split. Block = 128 threads, i-tile 128 rows, j-tile 32.
// Thread FMA tile: 4 rows x 16 dims, rows interleaved by 32:
//   cg = t&3  -> dims cg*16 .. cg*16+15
//   rg = t>>2 -> rows rg, rg+32, rg+64, rg+96
// p stored duplicated ({p,p}) -> LDS.64 feeds FFMA2 directly (no movs).
// Wh stored chunk-swizzled: logical 16B chunk c at position ((c&3)<<2)|(c>>2)
//   -> the 4 col-groups' LDS.128 hit distinct banks.
// ---------------------------------------------------------------------------
__global__ __launch_bounds__(128, 4) void k2_attn(const int* __restrict__ adj) {
    __shared__ unsigned long long p_dup[128][JT + 1];  // row stride 33 ull: conflict-free
    __shared__ float Wh_sm[JT][OUTD];                  // swizzled chunks

    const int t     = threadIdx.x;
    const int i0    = blockIdx.x * 128;
    const int split = blockIdx.y;
    const int js    = split * JCHUNK;
    const int cg = t & 3;
    const int rg = t >> 2;

    const float s1v = g_s1[i0 + t];
    const int* adjrow = adj + (size_t)(i0 + t) * NN + js;

    float lacc = 0.f;
    unsigned long long acc[4][8];
#pragma unroll
    for (int rr = 0; rr < 4; ++rr)
#pragma unroll
        for (int q = 0; q < 8; ++q) acc[rr][q] = 0ull;

    for (int tile = 0; tile < JCHUNK / JT; ++tile) {
        const int j0 = tile * JT;
        __syncthreads();   // previous tile fully consumed

        // Wh tile: 32 j x 64 d. Thread t: row t>>2, quarter t&3 (4 chunks), swizzled store.
        {
            const int jr = t >> 2, qc = t & 3;
            const float4* src = (const float4*)(g_Wh + (size_t)(js + j0 + jr) * OUTD + qc * 16);
#pragma unroll
            for (int u = 0; u < 4; ++u) {
                int c  = qc * 4 + u;
                int cs = ((c & 3) << 2) | (c >> 2);
                *(float4*)&Wh_sm[jr][cs * 4] = src[u];
            }
        }
        // p tile: thread t owns row t, 32 j
        {
            const int4*   a4p = (const int4*)(adjrow + j0);
            const float4* s4p = (const float4*)(g_s2 + js + j0);
#pragma unroll
            for (int k = 0; k < 8; ++k) {
                int4   a4 = a4p[k];
                float4 s4 = s4p[k];
                float e, pv;
                e = s1v + s4.x; e = fmaxf(e, 0.2f * e); pv = a4.x ? __expf(e) : 0.f;
                lacc += pv; sts_dup(&p_dup[t][4 * k + 0], pv);
                e = s1v + s4.y; e = fmaxf(e, 0.2f * e); pv = a4.y ? __expf(e) : 0.f;
                lacc += pv; sts_dup(&p_dup[t][4 * k + 1], pv);
                e = s1v + s4.z; e = fmaxf(e, 0.2f * e); pv = a4.z ? __expf(e) : 0.f;
                lacc += pv; sts_dup(&p_dup[t][4 * k + 2], pv);
                e = s1v + s4.w; e = fmaxf(e, 0.2f * e); pv = a4.w ? __expf(e) : 0.f;
                lacc += pv; sts_dup(&p_dup[t][4 * k + 3], pv);
            }
        }
        __syncthreads();

        // acc[rr][dims] += p[row_rr][j] * Wh[j][dims]
#pragma unroll 2
        for (int j = 0; j < JT; ++j) {
            unsigned long long pp0 = p_dup[rg +  0][j];
            unsigned long long pp1 = p_dup[rg + 32][j];
            unsigned long long pp2 = p_dup[rg + 64][j];
            unsigned long long pp3 = p_dup[rg + 96][j];
#pragma unroll
            for (int q = 0; q < 4; ++q) {
                const ulonglong2 w = *(const ulonglong2*)&Wh_sm[j][(q * 4 + cg) * 4];
                ffma2(acc[0][2 * q], w.x, pp0); ffma2(acc[0][2 * q + 1], w.y, pp0);
                ffma2(acc[1][2 * q], w.x, pp1); ffma2(acc[1][2 * q + 1], w.y, pp1);
                ffma2(acc[2][2 * q], w.x, pp2); ffma2(acc[2][2 * q + 1], w.y, pp2);
                ffma2(acc[3][2 * q], w.x, pp3); ffma2(acc[3][2 * q + 1], w.y, pp3);
            }
        }
    }

    g_lp[(size_t)split * NN + i0 + t] = lacc;

    // store partials: rows rg + 32*rr, dims cg*16..+15
#pragma unroll
    for (int rr = 0; rr < 4; ++rr) {
        const int row = i0 + rg + rr * 32;
        float* dst = &g_part[((size_t)split * NN + row) * OUTD + cg * 16];
#pragma unroll
        for (int q = 0; q < 4; ++q) {
            float2 a = upk2(acc[rr][2 * q]);
            float2 b = upk2(acc[rr][2 * q + 1]);
            *(float4*)&dst[4 * q] = make_float4(a.x, a.y, b.x, b.y);
        }
    }
}

// ---------------------------------------------------------------------------
// K3: reduce NSPLIT partials, normalize, ELU.
// ---------------------------------------------------------------------------
__global__ __launch_bounds__(128) void k3_reduce(float* __restrict__ out) {
    const int q   = blockIdx.x * 128 + threadIdx.x;
    const int row = q >> 4;
    const int c4  = (q & 15) * 4;

    float l = 0.f;
#pragma unroll
    for (int s = 0; s < NSPLIT; ++s) l += g_lp[(size_t)s * NN + row];
    const float inv = 1.0f / l;

    float4 acc = make_float4(0.f, 0.f, 0.f, 0.f);
#pragma unroll
    for (int s = 0; s < NSPLIT; ++s) {
        float4 v = *(const float4*)&g_part[((size_t)s * NN + row) * OUTD + c4];
        acc.x += v.x; acc.y += v.y; acc.z += v.z; acc.w += v.w;
    }
    acc.x *= inv; acc.y *= inv; acc.z *= inv; acc.w *= inv;
    acc.x = acc.x > 0.f ? acc.x : expm1f(acc.x);
    acc.y = acc.y > 0.f ? acc.y : expm1f(acc.y);
    acc.z = acc.z > 0.f ? acc.z : expm1f(acc.z);
    acc.w = acc.w > 0.f ? acc.w : expm1f(acc.w);
    *(float4*)&out[(size_t)row * OUTD + c4] = acc;
}

extern "C" void kernel_launch(void* const* d_in, const int* in_sizes, int n_in,
                              void* d_out, int out_size) {
    const float* x   = (const float*)d_in[0];
    const int*   adj = (const int*)d_in[1];
    const float* W   = (const float*)d_in[2];
    const float* a   = (const float*)d_in[3];
    float* out = (float*)d_out;

    k1_proj<<<256, 128>>>(x, W, a);
    k2_attn<<<dim3(NN / 128, NSPLIT), 128>>>(adj);
    k3_reduce<<<(NN * OUTD / 4) / 128, 128>>>(out);
}